// round 15
// baseline (speedup 1.0000x reference)
#include <cuda_runtime.h>
#include <cuda_bf16.h>
#include <cuda_fp16.h>
#include <math.h>
#include <cstdint>

#define NMAX 20000
#define HDIM 256
#define GNUM 64
#define BM 128
#define BN 128
#define KST 16
#define NKS (HDIM / KST)
#define AS_STRIDE 24
#define BS_STRIDE 136
#define PSPLIT 8
#define MAXDEG 128

// ---------------- scratch (device globals, no allocation) ----------------
__device__ int      g_cnt_out[NMAX];
__device__ int      g_cnt_in[NMAX];
__device__ int      g_nbr[NMAX * MAXDEG];
__device__ unsigned g_Wh2[HDIM * HDIM / 2];   // W hi-split, bf16x2 words
__device__ unsigned g_Wl2[HDIM * HDIM / 2];   // W lo-split, bf16x2 words
__device__ __half   g_hn[NMAX * HDIM];        // GEMM output, fp16
__device__ float    g_agg[NMAX * HDIM];
__device__ float    g_gate[NMAX];
__device__ int      g_counts[GNUM];
__device__ int      g_starts[GNUM + 1];

__device__ __forceinline__ unsigned bf2_as_u32(__nv_bfloat162 v) {
    return *reinterpret_cast<unsigned*>(&v);
}
__device__ __forceinline__ void split2(float a0, float a1, unsigned& hi, unsigned& lo) {
    __nv_bfloat162 h = __floats2bfloat162_rn(a0, a1);
    float r0 = a0 - __low2float(h);
    float r1 = a1 - __high2float(h);
    __nv_bfloat162 l = __floats2bfloat162_rn(r0, r1);
    hi = bf2_as_u32(h);
    lo = bf2_as_u32(l);
}

// ---------------- init: zero counters + pre-split W ----------------
__global__ void k_init(const float* __restrict__ W, int Nn) {
    int i = blockIdx.x * blockDim.x + threadIdx.x;
    if (i < Nn) { g_cnt_out[i] = 0; g_cnt_in[i] = 0; }
    if (i < GNUM) g_counts[i] = 0;
    float2 w = reinterpret_cast<const float2*>(W)[i];
    unsigned hi, lo;
    split2(w.x, w.y, hi, lo);
    g_Wh2[i] = hi;
    g_Wl2[i] = lo;
}

// ---------------- build: degrees + adjacency buckets + graph counts ----------------
__global__ void k_build(const int* __restrict__ src, const int* __restrict__ dst,
                        const int* __restrict__ gid, int E, int Nn) {
    int i = blockIdx.x * blockDim.x + threadIdx.x;
    if (i < E) {
        int s = src[i], d = dst[i];
        atomicAdd(&g_cnt_out[s], 1);
        int pos = atomicAdd(&g_cnt_in[d], 1);
        if (pos < MAXDEG) g_nbr[d * MAXDEG + pos] = s;
    }
    if (i < Nn) atomicAdd(&g_counts[gid[i]], 1);
}

// ---------------- parallel tiny scan ----------------
__global__ void k_scan() {
    __shared__ int c[GNUM];
    int t = threadIdx.x;
    c[t] = g_counts[t];
    __syncthreads();
    int s = 0;
    for (int i = 0; i < t; i++) s += c[i];
    g_starts[t] = s;
    if (t == GNUM - 1) g_starts[GNUM] = s + c[t];
}

// ---------------- async copy / mma helpers ----------------
__device__ __forceinline__ void cp16(void* smem, const void* gmem) {
    unsigned s = (unsigned)__cvta_generic_to_shared(smem);
    asm volatile("cp.async.cg.shared.global [%0], [%1], 16;" :: "r"(s), "l"(gmem));
}
__device__ __forceinline__ void cp_commit() { asm volatile("cp.async.commit_group;"); }
__device__ __forceinline__ void cp_wait1()  { asm volatile("cp.async.wait_group 1;"); }

__device__ __forceinline__ void ldmx4(unsigned* r, const void* p) {
    unsigned a = (unsigned)__cvta_generic_to_shared(p);
    asm volatile("ldmatrix.sync.aligned.m8n8.x4.shared.b16 {%0,%1,%2,%3}, [%4];"
                 : "=r"(r[0]), "=r"(r[1]), "=r"(r[2]), "=r"(r[3]) : "r"(a));
}
__device__ __forceinline__ void ldmx4t(unsigned* r, const void* p) {
    unsigned a = (unsigned)__cvta_generic_to_shared(p);
    asm volatile("ldmatrix.sync.aligned.m8n8.x4.trans.shared.b16 {%0,%1,%2,%3}, [%4];"
                 : "=r"(r[0]), "=r"(r[1]), "=r"(r[2]), "=r"(r[3]) : "r"(a));
}
__device__ __forceinline__ void mma_bf16(float* c, const unsigned* a, unsigned b0, unsigned b1) {
    asm volatile(
        "mma.sync.aligned.m16n8k16.row.col.f32.bf16.bf16.f32 "
        "{%0,%1,%2,%3},{%4,%5,%6,%7},{%8,%9},{%0,%1,%2,%3};"
        : "+f"(c[0]), "+f"(c[1]), "+f"(c[2]), "+f"(c[3])
        : "r"(a[0]), "r"(a[1]), "r"(a[2]), "r"(a[3]), "r"(b0), "r"(b1));
}

// ---------------- GEMM: hn = (h * rsqrt(max(deg_out,1))) @ W_conv ----------------
// split-bf16 tensor-core GEMM; 2-deep cp.async pipeline; A-convert off critical path
// (thread-local wait -> convert, single barrier per k-step); B triple-buffered.
__global__ void __launch_bounds__(256, 2)
k_gemm_hn(const float* __restrict__ h, int M) {
    __shared__ float rawA[2][BM][KST];                // 16 KB
    __shared__ __nv_bfloat16 Ah[2][BM][AS_STRIDE];    // 12 KB
    __shared__ __nv_bfloat16 Al[2][BM][AS_STRIDE];    // 12 KB
    __shared__ __nv_bfloat16 Bh[3][KST][BS_STRIDE];   // 12.75 KB
    __shared__ __nv_bfloat16 Bl[3][KST][BS_STRIDE];   // 12.75 KB

    int tid = threadIdx.x;
    int m0 = blockIdx.y * BM;
    int n0 = blockIdx.x * BN;

    int a_r = tid >> 1;
    int a_k = (tid & 1) * 8;
    int gm = m0 + a_r;
    bool a_ok = (gm < M);
    float scale = a_ok ? rsqrtf(fmaxf((float)g_cnt_out[gm], 1.0f)) : 0.0f;
    const float* hrow = h + (size_t)(a_ok ? gm : 0) * HDIM;

    int b_k = tid >> 4;
    int b_n = (tid & 15) * 8;
    int wbase = (b_k * HDIM + n0 + b_n) >> 1;

    int wid = tid >> 5, lane = tid & 31;
    int wm = (wid & 3) * 32;
    int wn = (wid >> 2) * 64;
    int mat = lane >> 3, mr = lane & 7;
    int a_row_off = (mat & 1) * 8 + mr;
    int a_col = (mat >> 1) * 8;
    int b_krow = (mat & 1) * 8 + mr;
    int b_ncol = (mat >> 1) * 8;

    float acc[2][8][4];
#pragma unroll
    for (int i = 0; i < 2; i++)
#pragma unroll
        for (int j = 0; j < 8; j++)
#pragma unroll
            for (int q = 0; q < 4; q++) acc[i][j][q] = 0.0f;

    // ---- prologue: stage 0 and stage 1 in flight ----
    cp16(&rawA[0][a_r][a_k],     hrow + a_k);
    cp16(&rawA[0][a_r][a_k + 4], hrow + a_k + 4);
    cp16(&Bh[0][b_k][b_n], g_Wh2 + wbase);
    cp16(&Bl[0][b_k][b_n], g_Wl2 + wbase);
    cp_commit();
    cp16(&rawA[1][a_r][a_k],     hrow + KST + a_k);
    cp16(&rawA[1][a_r][a_k + 4], hrow + KST + a_k + 4);
    cp16(&Bh[1][b_k][b_n], g_Wh2 + wbase + KST * (HDIM / 2));
    cp16(&Bl[1][b_k][b_n], g_Wl2 + wbase + KST * (HDIM / 2));
    cp_commit();

    int bcur = 0;   // ks % 3
    for (int ks = 0; ks < NKS; ks++) {
        int cur = ks & 1;
        // stage ks arrived (≤1 group may remain in flight = stage ks+1)
        cp_wait1();

        // ---- convert A stage ks (thread-local chunks: same thread cp'd them) ----
        {
            float4 v0 = *reinterpret_cast<const float4*>(&rawA[cur][a_r][a_k]);
            float4 v1 = *reinterpret_cast<const float4*>(&rawA[cur][a_r][a_k + 4]);
            uint4 uh, ul;
            split2(v0.x * scale, v0.y * scale, uh.x, ul.x);
            split2(v0.z * scale, v0.w * scale, uh.y, ul.y);
            split2(v1.x * scale, v1.y * scale, uh.z, ul.z);
            split2(v1.z * scale, v1.w * scale, uh.w, ul.w);
            *reinterpret_cast<uint4*>(&Ah[cur][a_r][a_k]) = uh;
            *reinterpret_cast<uint4*>(&Al[cur][a_r][a_k]) = ul;
        }
        __syncthreads();   // converts visible; all warps done mma(ks-1)

        // ---- issue stage ks+2 (rawA[cur] free per-thread; B[(ks+2)%3] last read at mma(ks-1)) ----
        if (ks + 2 < NKS) {
            int kn = (ks + 2) * KST;
            int bn2 = bcur + 2 >= 3 ? bcur - 1 : bcur + 2;   // (ks+2)%3
            cp16(&rawA[cur][a_r][a_k],     hrow + kn + a_k);
            cp16(&rawA[cur][a_r][a_k + 4], hrow + kn + a_k + 4);
            cp16(&Bh[bn2][b_k][b_n], g_Wh2 + wbase + kn * (HDIM / 2));
            cp16(&Bl[bn2][b_k][b_n], g_Wl2 + wbase + kn * (HDIM / 2));
            cp_commit();
        }

        // ---- mma stage ks ----
        unsigned a_h[2][4], a_l[2][4];
#pragma unroll
        for (int mi = 0; mi < 2; mi++) {
            ldmx4(a_h[mi], &Ah[cur][wm + mi * 16 + a_row_off][a_col]);
            ldmx4(a_l[mi], &Al[cur][wm + mi * 16 + a_row_off][a_col]);
        }
#pragma unroll
        for (int p = 0; p < 4; p++) {
            unsigned bh[4], bl[4];
            int nc = wn + p * 16 + b_ncol;
            ldmx4t(bh, &Bh[bcur][b_krow][nc]);
            ldmx4t(bl, &Bl[bcur][b_krow][nc]);
#pragma unroll
            for (int mi = 0; mi < 2; mi++) {
                float* c0 = acc[mi][2 * p];
                float* c1 = acc[mi][2 * p + 1];
                mma_bf16(c0, a_h[mi], bh[0], bh[1]);
                mma_bf16(c0, a_h[mi], bl[0], bl[1]);
                mma_bf16(c0, a_l[mi], bh[0], bh[1]);
                mma_bf16(c1, a_h[mi], bh[2], bh[3]);
                mma_bf16(c1, a_h[mi], bl[2], bl[3]);
                mma_bf16(c1, a_l[mi], bh[2], bh[3]);
            }
        }
        bcur = (bcur + 1 >= 3) ? 0 : bcur + 1;
    }

    // ---- epilogue: fp16 ----
    int row0 = m0 + wm + (lane >> 2);
    int col0 = n0 + wn + (lane & 3) * 2;
#pragma unroll
    for (int mi = 0; mi < 2; mi++) {
#pragma unroll
        for (int nf = 0; nf < 8; nf++) {
            int r = row0 + mi * 16;
            int c = col0 + nf * 8;
            if (r < M)
                *reinterpret_cast<__half2*>(g_hn + (size_t)r * HDIM + c) =
                    __floats2half2_rn(acc[mi][nf][0], acc[mi][nf][1]);
            if (r + 8 < M)
                *reinterpret_cast<__half2*>(g_hn + (size_t)(r + 8) * HDIM + c) =
                    __floats2half2_rn(acc[mi][nf][2], acc[mi][nf][3]);
        }
    }
}

// ---------------- fused aggregate + scale + bias + relu + gate (R14 proven) ----------------
__global__ void k_agg(const float* __restrict__ b_conv,
                      const float* __restrict__ w_gate,
                      const float* __restrict__ b_gate) {
    int n = blockIdx.x;
    int tid = threadIdx.x;
    __shared__ int nbr_s[MAXDEG];
    __shared__ float4 part[256];
    __shared__ float red[64];

    int deg = g_cnt_in[n];
    int cnt = min(deg, MAXDEG);
    if (tid < cnt) nbr_s[tid] = g_nbr[n * MAXDEG + tid];
    __syncthreads();

    int fq = tid & 63;      // feature quad (4 halves = 8 bytes)
    int grp = tid >> 6;     // neighbor group 0..3
    float4 a = make_float4(0.f, 0.f, 0.f, 0.f);
    int j = grp;
    for (; j + 8 <= cnt; j += 8) {
        unsigned long long r0 = __ldg(reinterpret_cast<const unsigned long long*>(
            g_hn + (size_t)nbr_s[j] * HDIM) + fq);
        unsigned long long r1 = __ldg(reinterpret_cast<const unsigned long long*>(
            g_hn + (size_t)nbr_s[j + 4] * HDIM) + fq);
        const __half2* p0 = reinterpret_cast<const __half2*>(&r0);
        const __half2* p1 = reinterpret_cast<const __half2*>(&r1);
        float2 f00 = __half22float2(p0[0]), f01 = __half22float2(p0[1]);
        float2 f10 = __half22float2(p1[0]), f11 = __half22float2(p1[1]);
        a.x += f00.x + f10.x; a.y += f00.y + f10.y;
        a.z += f01.x + f11.x; a.w += f01.y + f11.y;
    }
    for (; j < cnt; j += 4) {
        unsigned long long r0 = __ldg(reinterpret_cast<const unsigned long long*>(
            g_hn + (size_t)nbr_s[j] * HDIM) + fq);
        const __half2* p0 = reinterpret_cast<const __half2*>(&r0);
        float2 f0 = __half22float2(p0[0]), f1 = __half22float2(p0[1]);
        a.x += f0.x; a.y += f0.y; a.z += f1.x; a.w += f1.y;
    }
    part[tid] = a;
    __syncthreads();
    if (tid < 128) {
        float4 b = part[tid + 128];
        float4 s = part[tid];
        s.x += b.x; s.y += b.y; s.z += b.z; s.w += b.w;
        part[tid] = s;
    }
    __syncthreads();
    if (tid < 64) {
        float4 b = part[tid + 64];
        float4 s = part[tid];
        s.x += b.x; s.y += b.y; s.z += b.z; s.w += b.w;
        float sc = rsqrtf(fmaxf((float)deg, 1.0f));
        float4 bc = __ldg(reinterpret_cast<const float4*>(b_conv) + tid);
        float4 v;
        v.x = fmaxf(s.x * sc + bc.x, 0.0f);
        v.y = fmaxf(s.y * sc + bc.y, 0.0f);
        v.z = fmaxf(s.z * sc + bc.z, 0.0f);
        v.w = fmaxf(s.w * sc + bc.w, 0.0f);
        reinterpret_cast<float4*>(g_agg + (size_t)n * HDIM)[tid] = v;
        float4 wg = __ldg(reinterpret_cast<const float4*>(w_gate) + tid);
        red[tid] = v.x * wg.x + v.y * wg.y + v.z * wg.z + v.w * wg.w;
    }
    __syncthreads();
    if (tid < 32) {
        float r = red[tid] + red[tid + 32];
#pragma unroll
        for (int off = 16; off > 0; off >>= 1)
            r += __shfl_down_sync(0xffffffffu, r, off);
        if (tid == 0) g_gate[n] = r + b_gate[0];
    }
}

// ---------------- segment softmax ----------------
__global__ void k_soft(float* __restrict__ att_out, float* __restrict__ hg_out) {
    int g = blockIdx.x;
    int tid = threadIdx.x;
    hg_out[(size_t)g * HDIM + tid] = 0.0f;
    int s = g_starts[g], e = g_starts[g + 1];
    if (s >= e) return;
    __shared__ float red[256];

    float m = -INFINITY;
    for (int n = s + tid; n < e; n += 256) m = fmaxf(m, g_gate[n]);
    red[tid] = m; __syncthreads();
#pragma unroll
    for (int st = 128; st > 0; st >>= 1) {
        if (tid < st) red[tid] = fmaxf(red[tid], red[tid + st]);
        __syncthreads();
    }
    float gm = red[0];
    __syncthreads();
    float sm = 0.0f;
    for (int n = s + tid; n < e; n += 256) {
        float ev = __expf(g_gate[n] - gm);
        att_out[n] = ev;
        sm += ev;
    }
    red[tid] = sm; __syncthreads();
#pragma unroll
    for (int st = 128; st > 0; st >>= 1) {
        if (tid < st) red[tid] += red[tid + st];
        __syncthreads();
    }
    float inv = 1.0f / red[0];
    __syncthreads();
    for (int n = s + tid; n < e; n += 256) att_out[n] *= inv;
}

// ---------------- weighted sum (float4 gathers) ----------------
__global__ void k_wsum(const float* __restrict__ att, float* __restrict__ hg_out) {
    int g = blockIdx.x;
    int sp = blockIdx.y;
    int tid = threadIdx.x;
    int s = g_starts[g], e = g_starts[g + 1];
    int cnt = e - s;
    if (cnt <= 0) return;
    int chunk = (cnt + PSPLIT - 1) / PSPLIT;
    int beg = s + sp * chunk;
    int end = min(e, beg + chunk);
    if (beg >= end) return;

    __shared__ float4 part[256];
    int fq = tid & 63;
    int grp = tid >> 6;
    float4 c = make_float4(0.f, 0.f, 0.f, 0.f);
    for (int n = beg + grp; n < end; n += 4) {
        float a = att[n];
        float4 v = __ldg(reinterpret_cast<const float4*>(g_agg + (size_t)n * HDIM) + fq);
        c.x += a * v.x; c.y += a * v.y; c.z += a * v.z; c.w += a * v.w;
    }
    part[tid] = c;
    __syncthreads();
    if (tid < 128) {
        float4 b = part[tid + 128];
        float4 t = part[tid];
        t.x += b.x; t.y += b.y; t.z += b.z; t.w += b.w;
        part[tid] = t;
    }
    __syncthreads();
    if (tid < 64) {
        float4 b = part[tid + 64];
        float4 t = part[tid];
        t.x += b.x; t.y += b.y; t.z += b.z; t.w += b.w;
        float* hp = hg_out + (size_t)g * HDIM + tid * 4;
        atomicAdd(hp + 0, t.x);
        atomicAdd(hp + 1, t.y);
        atomicAdd(hp + 2, t.z);
        atomicAdd(hp + 3, t.w);
    }
}

// ---------------- classifier heads ----------------
__global__ void k_heads(const float* __restrict__ hg,
                        const float* __restrict__ W1, const float* __restrict__ b1,
                        const float* __restrict__ W2, const float* __restrict__ b2,
                        float* __restrict__ probs) {
    int g = blockIdx.x;
    int j = threadIdx.x;
    __shared__ float s_hg[256];
    __shared__ float r0[256], r1[256];
    s_hg[j] = hg[(size_t)g * HDIM + j];
    __syncthreads();
    float acc = b1[j];
#pragma unroll 8
    for (int k = 0; k < HDIM; k++) acc += s_hg[k] * W1[(size_t)k * HDIM + j];
    r0[j] = acc * W2[j * 2 + 0];
    r1[j] = acc * W2[j * 2 + 1];
    __syncthreads();
#pragma unroll
    for (int st = 128; st > 0; st >>= 1) {
        if (j < st) { r0[j] += r0[j + st]; r1[j] += r1[j + st]; }
        __syncthreads();
    }
    if (j == 0) {
        probs[g * 2 + 0] = 1.0f / (1.0f + expf(-(r0[0] + b2[0])));
        probs[g * 2 + 1] = 1.0f / (1.0f + expf(-(r1[0] + b2[1])));
    }
}

// ---------------- launch ----------------
extern "C" void kernel_launch(void* const* d_in, const int* in_sizes, int n_in,
                              void* d_out, int out_size) {
    const float* h      = (const float*)d_in[0];
    const int*   src    = (const int*)d_in[1];
    const int*   dst    = (const int*)d_in[2];
    const int*   gid    = (const int*)d_in[3];
    const float* W_conv = (const float*)d_in[4];
    const float* b_conv = (const float*)d_in[5];
    const float* w_gate = (const float*)d_in[6];
    const float* b_gate = (const float*)d_in[7];
    const float* W1     = (const float*)d_in[8];
    const float* b1     = (const float*)d_in[9];
    const float* W2     = (const float*)d_in[10];
    const float* b2     = (const float*)d_in[11];

    int Nn = in_sizes[3];
    int E  = in_sizes[1];

    float* out   = (float*)d_out;
    float* probs = out;
    float* att   = out + GNUM * 2;
    float* hg    = out + GNUM * 2 + Nn;

    int NE = E > Nn ? E : Nn;
    k_init<<<HDIM * HDIM / 2 / 256, 256>>>(W_conv, Nn);
    k_build<<<(NE + 255) / 256, 256>>>(src, dst, gid, E, Nn);
    k_scan<<<1, GNUM>>>();
    dim3 gg(HDIM / BN, (Nn + BM - 1) / BM);
    k_gemm_hn<<<gg, 256>>>(h, Nn);
    k_agg<<<Nn, 256>>>(b_conv, w_gate, b_gate);
    k_soft<<<GNUM, 256>>>(att, hg);
    dim3 pw(GNUM, PSPLIT);
    k_wsum<<<pw, 256>>>(att, hg);
    k_heads<<<GNUM, 256>>>(hg, W1, b1, W2, b2, probs);
}

// round 16
// speedup vs baseline: 1.1640x; 1.1640x over previous
#include <cuda_runtime.h>
#include <cuda_bf16.h>
#include <cuda_fp16.h>
#include <math.h>
#include <cstdint>

#define NMAX 20000
#define HDIM 256
#define GNUM 64
#define BM 128
#define BN 128
#define KST 16
#define NKS (HDIM / KST)
#define AS_STRIDE 24
#define BS_STRIDE 136
#define PSPLIT 8
#define MAXDEG 128

// ---------------- scratch (device globals, no allocation) ----------------
__device__ int      g_cnt_out[NMAX];
__device__ int      g_cnt_in[NMAX];
__device__ int      g_nbr[NMAX * MAXDEG];
__device__ unsigned g_Wh2[HDIM * HDIM / 2];   // W hi-split, bf16x2 words
__device__ unsigned g_Wl2[HDIM * HDIM / 2];   // W lo-split, bf16x2 words
__device__ __half   g_hn[NMAX * HDIM];        // GEMM output, fp16
__device__ float    g_agg[NMAX * HDIM];
__device__ float    g_gate[NMAX];
__device__ int      g_counts[GNUM];
__device__ int      g_starts[GNUM + 1];

__device__ __forceinline__ unsigned bf2_as_u32(__nv_bfloat162 v) {
    return *reinterpret_cast<unsigned*>(&v);
}
__device__ __forceinline__ void split2(float a0, float a1, unsigned& hi, unsigned& lo) {
    __nv_bfloat162 h = __floats2bfloat162_rn(a0, a1);
    float r0 = a0 - __low2float(h);
    float r1 = a1 - __high2float(h);
    __nv_bfloat162 l = __floats2bfloat162_rn(r0, r1);
    hi = bf2_as_u32(h);
    lo = bf2_as_u32(l);
}

// ---------------- init: zero counters + pre-split W ----------------
__global__ void k_init(const float* __restrict__ W, int Nn) {
    int i = blockIdx.x * blockDim.x + threadIdx.x;
    if (i < Nn) { g_cnt_out[i] = 0; g_cnt_in[i] = 0; }
    if (i < GNUM) g_counts[i] = 0;
    float2 w = reinterpret_cast<const float2*>(W)[i];
    unsigned hi, lo;
    split2(w.x, w.y, hi, lo);
    g_Wh2[i] = hi;
    g_Wl2[i] = lo;
}

// ---------------- build: degrees + adjacency buckets + graph counts ----------------
__global__ void k_build(const int* __restrict__ src, const int* __restrict__ dst,
                        const int* __restrict__ gid, int E, int Nn) {
    int i = blockIdx.x * blockDim.x + threadIdx.x;
    if (i < E) {
        int s = src[i], d = dst[i];
        atomicAdd(&g_cnt_out[s], 1);
        int pos = atomicAdd(&g_cnt_in[d], 1);
        if (pos < MAXDEG) g_nbr[d * MAXDEG + pos] = s;
    }
    if (i < Nn) atomicAdd(&g_counts[gid[i]], 1);
}

// ---------------- parallel tiny scan ----------------
__global__ void k_scan() {
    __shared__ int c[GNUM];
    int t = threadIdx.x;
    c[t] = g_counts[t];
    __syncthreads();
    int s = 0;
    for (int i = 0; i < t; i++) s += c[i];
    g_starts[t] = s;
    if (t == GNUM - 1) g_starts[GNUM] = s + c[t];
}

// ---------------- async copy / mma helpers ----------------
__device__ __forceinline__ void cp16(void* smem, const void* gmem) {
    unsigned s = (unsigned)__cvta_generic_to_shared(smem);
    asm volatile("cp.async.cg.shared.global [%0], [%1], 16;" :: "r"(s), "l"(gmem));
}
__device__ __forceinline__ void cp_commit() { asm volatile("cp.async.commit_group;"); }
__device__ __forceinline__ void cp_wait1()  { asm volatile("cp.async.wait_group 1;"); }

__device__ __forceinline__ void ldmx4(unsigned* r, const void* p) {
    unsigned a = (unsigned)__cvta_generic_to_shared(p);
    asm volatile("ldmatrix.sync.aligned.m8n8.x4.shared.b16 {%0,%1,%2,%3}, [%4];"
                 : "=r"(r[0]), "=r"(r[1]), "=r"(r[2]), "=r"(r[3]) : "r"(a));
}
__device__ __forceinline__ void ldmx4t(unsigned* r, const void* p) {
    unsigned a = (unsigned)__cvta_generic_to_shared(p);
    asm volatile("ldmatrix.sync.aligned.m8n8.x4.trans.shared.b16 {%0,%1,%2,%3}, [%4];"
                 : "=r"(r[0]), "=r"(r[1]), "=r"(r[2]), "=r"(r[3]) : "r"(a));
}
__device__ __forceinline__ void mma_bf16(float* c, const unsigned* a, unsigned b0, unsigned b1) {
    asm volatile(
        "mma.sync.aligned.m16n8k16.row.col.f32.bf16.bf16.f32 "
        "{%0,%1,%2,%3},{%4,%5,%6,%7},{%8,%9},{%0,%1,%2,%3};"
        : "+f"(c[0]), "+f"(c[1]), "+f"(c[2]), "+f"(c[3])
        : "r"(a[0]), "r"(a[1]), "r"(a[2]), "r"(a[3]), "r"(b0), "r"(b1));
}

// ---------------- GEMM: hn = (h * rsqrt(max(deg_out,1))) @ W_conv ----------------
// split-bf16 tensor-core GEMM (R15): 2-deep cp.async pipeline, 1 barrier/k-step.
__global__ void __launch_bounds__(256, 2)
k_gemm_hn(const float* __restrict__ h, int M) {
    __shared__ float rawA[2][BM][KST];
    __shared__ __nv_bfloat16 Ah[2][BM][AS_STRIDE];
    __shared__ __nv_bfloat16 Al[2][BM][AS_STRIDE];
    __shared__ __nv_bfloat16 Bh[3][KST][BS_STRIDE];
    __shared__ __nv_bfloat16 Bl[3][KST][BS_STRIDE];

    int tid = threadIdx.x;
    int m0 = blockIdx.y * BM;
    int n0 = blockIdx.x * BN;

    int a_r = tid >> 1;
    int a_k = (tid & 1) * 8;
    int gm = m0 + a_r;
    bool a_ok = (gm < M);
    float scale = a_ok ? rsqrtf(fmaxf((float)g_cnt_out[gm], 1.0f)) : 0.0f;
    const float* hrow = h + (size_t)(a_ok ? gm : 0) * HDIM;

    int b_k = tid >> 4;
    int b_n = (tid & 15) * 8;
    int wbase = (b_k * HDIM + n0 + b_n) >> 1;

    int wid = tid >> 5, lane = tid & 31;
    int wm = (wid & 3) * 32;
    int wn = (wid >> 2) * 64;
    int mat = lane >> 3, mr = lane & 7;
    int a_row_off = (mat & 1) * 8 + mr;
    int a_col = (mat >> 1) * 8;
    int b_krow = (mat & 1) * 8 + mr;
    int b_ncol = (mat >> 1) * 8;

    float acc[2][8][4];
#pragma unroll
    for (int i = 0; i < 2; i++)
#pragma unroll
        for (int j = 0; j < 8; j++)
#pragma unroll
            for (int q = 0; q < 4; q++) acc[i][j][q] = 0.0f;

    cp16(&rawA[0][a_r][a_k],     hrow + a_k);
    cp16(&rawA[0][a_r][a_k + 4], hrow + a_k + 4);
    cp16(&Bh[0][b_k][b_n], g_Wh2 + wbase);
    cp16(&Bl[0][b_k][b_n], g_Wl2 + wbase);
    cp_commit();
    cp16(&rawA[1][a_r][a_k],     hrow + KST + a_k);
    cp16(&rawA[1][a_r][a_k + 4], hrow + KST + a_k + 4);
    cp16(&Bh[1][b_k][b_n], g_Wh2 + wbase + KST * (HDIM / 2));
    cp16(&Bl[1][b_k][b_n], g_Wl2 + wbase + KST * (HDIM / 2));
    cp_commit();

    int bcur = 0;
    for (int ks = 0; ks < NKS; ks++) {
        int cur = ks & 1;
        cp_wait1();

        {
            float4 v0 = *reinterpret_cast<const float4*>(&rawA[cur][a_r][a_k]);
            float4 v1 = *reinterpret_cast<const float4*>(&rawA[cur][a_r][a_k + 4]);
            uint4 uh, ul;
            split2(v0.x * scale, v0.y * scale, uh.x, ul.x);
            split2(v0.z * scale, v0.w * scale, uh.y, ul.y);
            split2(v1.x * scale, v1.y * scale, uh.z, ul.z);
            split2(v1.z * scale, v1.w * scale, uh.w, ul.w);
            *reinterpret_cast<uint4*>(&Ah[cur][a_r][a_k]) = uh;
            *reinterpret_cast<uint4*>(&Al[cur][a_r][a_k]) = ul;
        }
        __syncthreads();

        if (ks + 2 < NKS) {
            int kn = (ks + 2) * KST;
            int bn2 = bcur + 2 >= 3 ? bcur - 1 : bcur + 2;
            cp16(&rawA[cur][a_r][a_k],     hrow + kn + a_k);
            cp16(&rawA[cur][a_r][a_k + 4], hrow + kn + a_k + 4);
            cp16(&Bh[bn2][b_k][b_n], g_Wh2 + wbase + kn * (HDIM / 2));
            cp16(&Bl[bn2][b_k][b_n], g_Wl2 + wbase + kn * (HDIM / 2));
            cp_commit();
        }

        unsigned a_h[2][4], a_l[2][4];
#pragma unroll
        for (int mi = 0; mi < 2; mi++) {
            ldmx4(a_h[mi], &Ah[cur][wm + mi * 16 + a_row_off][a_col]);
            ldmx4(a_l[mi], &Al[cur][wm + mi * 16 + a_row_off][a_col]);
        }
#pragma unroll
        for (int p = 0; p < 4; p++) {
            unsigned bh[4], bl[4];
            int nc = wn + p * 16 + b_ncol;
            ldmx4t(bh, &Bh[bcur][b_krow][nc]);
            ldmx4t(bl, &Bl[bcur][b_krow][nc]);
#pragma unroll
            for (int mi = 0; mi < 2; mi++) {
                float* c0 = acc[mi][2 * p];
                float* c1 = acc[mi][2 * p + 1];
                mma_bf16(c0, a_h[mi], bh[0], bh[1]);
                mma_bf16(c0, a_h[mi], bl[0], bl[1]);
                mma_bf16(c0, a_l[mi], bh[0], bh[1]);
                mma_bf16(c1, a_h[mi], bh[2], bh[3]);
                mma_bf16(c1, a_h[mi], bl[2], bl[3]);
                mma_bf16(c1, a_l[mi], bh[2], bh[3]);
            }
        }
        bcur = (bcur + 1 >= 3) ? 0 : bcur + 1;
    }

    int row0 = m0 + wm + (lane >> 2);
    int col0 = n0 + wn + (lane & 3) * 2;
#pragma unroll
    for (int mi = 0; mi < 2; mi++) {
#pragma unroll
        for (int nf = 0; nf < 8; nf++) {
            int r = row0 + mi * 16;
            int c = col0 + nf * 8;
            if (r < M)
                *reinterpret_cast<__half2*>(g_hn + (size_t)r * HDIM + c) =
                    __floats2half2_rn(acc[mi][nf][0], acc[mi][nf][1]);
            if (r + 8 < M)
                *reinterpret_cast<__half2*>(g_hn + (size_t)(r + 8) * HDIM + c) =
                    __floats2half2_rn(acc[mi][nf][2], acc[mi][nf][3]);
        }
    }
}

// ---------------- fused aggregate: WARP PER NODE ----------------
// lane owns features [8*lane, 8*lane+8); no smem, no barriers; gate via shuffle.
__global__ void k_agg(const float* __restrict__ b_conv,
                      const float* __restrict__ w_gate,
                      const float* __restrict__ b_gate, int Nn) {
    int n = (blockIdx.x * blockDim.x + threadIdx.x) >> 5;
    if (n >= Nn) return;
    int lane = threadIdx.x & 31;

    int deg = g_cnt_in[n];
    int cnt = min(deg, MAXDEG);
    const int* nb = g_nbr + n * MAXDEG;

    float f0 = 0.f, f1 = 0.f, f2 = 0.f, f3 = 0.f;
    float f4 = 0.f, f5 = 0.f, f6 = 0.f, f7 = 0.f;

    int j = 0;
    for (; j + 4 <= cnt; j += 4) {
        int s0 = __ldg(nb + j + 0);
        int s1 = __ldg(nb + j + 1);
        int s2 = __ldg(nb + j + 2);
        int s3 = __ldg(nb + j + 3);
        uint4 r0 = __ldg(reinterpret_cast<const uint4*>(g_hn + (size_t)s0 * HDIM) + lane);
        uint4 r1 = __ldg(reinterpret_cast<const uint4*>(g_hn + (size_t)s1 * HDIM) + lane);
        uint4 r2 = __ldg(reinterpret_cast<const uint4*>(g_hn + (size_t)s2 * HDIM) + lane);
        uint4 r3 = __ldg(reinterpret_cast<const uint4*>(g_hn + (size_t)s3 * HDIM) + lane);
#define ACC8(r) { \
        const __half2* p = reinterpret_cast<const __half2*>(&(r)); \
        float2 a0 = __half22float2(p[0]); float2 a1 = __half22float2(p[1]); \
        float2 a2 = __half22float2(p[2]); float2 a3 = __half22float2(p[3]); \
        f0 += a0.x; f1 += a0.y; f2 += a1.x; f3 += a1.y; \
        f4 += a2.x; f5 += a2.y; f6 += a3.x; f7 += a3.y; }
        ACC8(r0) ACC8(r1) ACC8(r2) ACC8(r3)
    }
    for (; j < cnt; j++) {
        int s0 = __ldg(nb + j);
        uint4 r0 = __ldg(reinterpret_cast<const uint4*>(g_hn + (size_t)s0 * HDIM) + lane);
        ACC8(r0)
    }
#undef ACC8

    float sc = rsqrtf(fmaxf((float)deg, 1.0f));
    float4 bc0 = __ldg(reinterpret_cast<const float4*>(b_conv) + lane * 2);
    float4 bc1 = __ldg(reinterpret_cast<const float4*>(b_conv) + lane * 2 + 1);
    float4 v0, v1;
    v0.x = fmaxf(f0 * sc + bc0.x, 0.0f);
    v0.y = fmaxf(f1 * sc + bc0.y, 0.0f);
    v0.z = fmaxf(f2 * sc + bc0.z, 0.0f);
    v0.w = fmaxf(f3 * sc + bc0.w, 0.0f);
    v1.x = fmaxf(f4 * sc + bc1.x, 0.0f);
    v1.y = fmaxf(f5 * sc + bc1.y, 0.0f);
    v1.z = fmaxf(f6 * sc + bc1.z, 0.0f);
    v1.w = fmaxf(f7 * sc + bc1.w, 0.0f);
    float4* op = reinterpret_cast<float4*>(g_agg + (size_t)n * HDIM);
    op[lane * 2]     = v0;
    op[lane * 2 + 1] = v1;

    float4 wg0 = __ldg(reinterpret_cast<const float4*>(w_gate) + lane * 2);
    float4 wg1 = __ldg(reinterpret_cast<const float4*>(w_gate) + lane * 2 + 1);
    float r = v0.x * wg0.x + v0.y * wg0.y + v0.z * wg0.z + v0.w * wg0.w
            + v1.x * wg1.x + v1.y * wg1.y + v1.z * wg1.z + v1.w * wg1.w;
#pragma unroll
    for (int off = 16; off > 0; off >>= 1)
        r += __shfl_down_sync(0xffffffffu, r, off);
    if (lane == 0) g_gate[n] = r + b_gate[0];
}

// ---------------- segment softmax ----------------
__global__ void k_soft(float* __restrict__ att_out, float* __restrict__ hg_out) {
    int g = blockIdx.x;
    int tid = threadIdx.x;
    hg_out[(size_t)g * HDIM + tid] = 0.0f;
    int s = g_starts[g], e = g_starts[g + 1];
    if (s >= e) return;
    __shared__ float red[256];

    float m = -INFINITY;
    for (int n = s + tid; n < e; n += 256) m = fmaxf(m, g_gate[n]);
    red[tid] = m; __syncthreads();
#pragma unroll
    for (int st = 128; st > 0; st >>= 1) {
        if (tid < st) red[tid] = fmaxf(red[tid], red[tid + st]);
        __syncthreads();
    }
    float gm = red[0];
    __syncthreads();
    float sm = 0.0f;
    for (int n = s + tid; n < e; n += 256) {
        float ev = __expf(g_gate[n] - gm);
        att_out[n] = ev;
        sm += ev;
    }
    red[tid] = sm; __syncthreads();
#pragma unroll
    for (int st = 128; st > 0; st >>= 1) {
        if (tid < st) red[tid] += red[tid + st];
        __syncthreads();
    }
    float inv = 1.0f / red[0];
    __syncthreads();
    for (int n = s + tid; n < e; n += 256) att_out[n] *= inv;
}

// ---------------- weighted sum (float4 gathers) ----------------
__global__ void k_wsum(const float* __restrict__ att, float* __restrict__ hg_out) {
    int g = blockIdx.x;
    int sp = blockIdx.y;
    int tid = threadIdx.x;
    int s = g_starts[g], e = g_starts[g + 1];
    int cnt = e - s;
    if (cnt <= 0) return;
    int chunk = (cnt + PSPLIT - 1) / PSPLIT;
    int beg = s + sp * chunk;
    int end = min(e, beg + chunk);
    if (beg >= end) return;

    __shared__ float4 part[256];
    int fq = tid & 63;
    int grp = tid >> 6;
    float4 c = make_float4(0.f, 0.f, 0.f, 0.f);
    for (int n = beg + grp; n < end; n += 4) {
        float a = att[n];
        float4 v = __ldg(reinterpret_cast<const float4*>(g_agg + (size_t)n * HDIM) + fq);
        c.x += a * v.x; c.y += a * v.y; c.z += a * v.z; c.w += a * v.w;
    }
    part[tid] = c;
    __syncthreads();
    if (tid < 128) {
        float4 b = part[tid + 128];
        float4 t = part[tid];
        t.x += b.x; t.y += b.y; t.z += b.z; t.w += b.w;
        part[tid] = t;
    }
    __syncthreads();
    if (tid < 64) {
        float4 b = part[tid + 64];
        float4 t = part[tid];
        t.x += b.x; t.y += b.y; t.z += b.z; t.w += b.w;
        float* hp = hg_out + (size_t)g * HDIM + tid * 4;
        atomicAdd(hp + 0, t.x);
        atomicAdd(hp + 1, t.y);
        atomicAdd(hp + 2, t.z);
        atomicAdd(hp + 3, t.w);
    }
}

// ---------------- classifier heads ----------------
__global__ void k_heads(const float* __restrict__ hg,
                        const float* __restrict__ W1, const float* __restrict__ b1,
                        const float* __restrict__ W2, const float* __restrict__ b2,
                        float* __restrict__ probs) {
    int g = blockIdx.x;
    int j = threadIdx.x;
    __shared__ float s_hg[256];
    __shared__ float r0[256], r1[256];
    s_hg[j] = hg[(size_t)g * HDIM + j];
    __syncthreads();
    float acc = b1[j];
#pragma unroll 8
    for (int k = 0; k < HDIM; k++) acc += s_hg[k] * W1[(size_t)k * HDIM + j];
    r0[j] = acc * W2[j * 2 + 0];
    r1[j] = acc * W2[j * 2 + 1];
    __syncthreads();
#pragma unroll
    for (int st = 128; st > 0; st >>= 1) {
        if (j < st) { r0[j] += r0[j + st]; r1[j] += r1[j + st]; }
        __syncthreads();
    }
    if (j == 0) {
        probs[g * 2 + 0] = 1.0f / (1.0f + expf(-(r0[0] + b2[0])));
        probs[g * 2 + 1] = 1.0f / (1.0f + expf(-(r1[0] + b2[1])));
    }
}

// ---------------- launch ----------------
extern "C" void kernel_launch(void* const* d_in, const int* in_sizes, int n_in,
                              void* d_out, int out_size) {
    const float* h      = (const float*)d_in[0];
    const int*   src    = (const int*)d_in[1];
    const int*   dst    = (const int*)d_in[2];
    const int*   gid    = (const int*)d_in[3];
    const float* W_conv = (const float*)d_in[4];
    const float* b_conv = (const float*)d_in[5];
    const float* w_gate = (const float*)d_in[6];
    const float* b_gate = (const float*)d_in[7];
    const float* W1     = (const float*)d_in[8];
    const float* b1     = (const float*)d_in[9];
    const float* W2     = (const float*)d_in[10];
    const float* b2     = (const float*)d_in[11];

    int Nn = in_sizes[3];
    int E  = in_sizes[1];

    float* out   = (float*)d_out;
    float* probs = out;
    float* att   = out + GNUM * 2;
    float* hg    = out + GNUM * 2 + Nn;

    int NE = E > Nn ? E : Nn;
    k_init<<<HDIM * HDIM / 2 / 256, 256>>>(W_conv, Nn);
    k_build<<<(NE + 255) / 256, 256>>>(src, dst, gid, E, Nn);
    k_scan<<<1, GNUM>>>();
    dim3 gg(HDIM / BN, (Nn + BM - 1) / BM);
    k_gemm_hn<<<gg, 256>>>(h, Nn);
    k_agg<<<(Nn * 32 + 255) / 256, 256>>>(b_conv, w_gate, b_gate, Nn);
    k_soft<<<GNUM, 256>>>(att, hg);
    dim3 pw(GNUM, PSPLIT);
    k_wsum<<<pw, 256>>>(att, hg);
    k_heads<<<GNUM, 256>>>(hg, W1, b1, W2, b2, probs);
}